// round 13
// baseline (speedup 1.0000x reference)
#include <cuda_runtime.h>
#include <cuda_bf16.h>
#include <cstdint>

#define FMAX 20908
#define NCTA 1036           // 148 SMs x 7 CTAs guaranteed co-resident

// Repacked per-face record: 4 x float4 = 64B, 128B-aligned so each record
// lies in one 128B line.
// chunk0=(t00,t01,t02,t10) chunk1=(t11,t12,t20,t21) chunk2=(t22,n0,n1,n2) chunk3=pad
__device__ __align__(128) float4 g_face_pack[FMAX * 4];

__global__ __launch_bounds__(256) void repack_kernel(
    const float* __restrict__ triangles,    // [F,3,3]
    const float* __restrict__ face_normals, // [F,3]
    int F)
{
    int i = blockIdx.x * blockDim.x + threadIdx.x;
    if (i >= F * 3) return;
    int f = i / 3;
    int c = i - 3 * f;
    const float* t = triangles + (size_t)f * 9;
    float4 v;
    if (c == 0)      v = make_float4(t[0], t[1], t[2], t[3]);
    else if (c == 1) v = make_float4(t[4], t[5], t[6], t[7]);
    else {
        const float* n = face_normals + (size_t)f * 3;
        v = make_float4(t[8], n[0], n[1], n[2]);
    }
    g_face_pack[4*f + c] = v;
}

__device__ __forceinline__ void cp_async16(uint32_t smem_addr, const void* gptr) {
    asm volatile("cp.async.ca.shared.global [%0], [%1], 16;"
                 :: "r"(smem_addr), "l"(gptr) : "memory");
}
__device__ __forceinline__ void cp_commit() {
    asm volatile("cp.async.commit_group;" ::: "memory");
}
__device__ __forceinline__ void cp_wait0() {
    asm volatile("cp.async.wait_group 0;" ::: "memory");
}

// Issue the cooperative gather for warp-tile wt into the given smem slot.
// lane 4p+c copies chunk c (c<3) of point p; face idx via L1-hot LDG.
__device__ __forceinline__ void issue_gather(
    const int* __restrict__ closest_faces,
    int wt, int Q, int c, int pgrp, uint32_t slot_addr)
{
    int base = wt << 5;
    #pragma unroll
    for (int r = 0; r < 4; r++) {
        int p_local = 8*r + pgrp;
        int idx = base + p_local;
        if (idx >= Q) idx = Q - 1;
        int fp = closest_faces[idx];
        if (c < 3) {
            cp_async16(slot_addr + (uint32_t)(p_local * 48 + c * 16),
                       &g_face_pack[4*(size_t)fp + c]);
        }
    }
}

// Persistent kernel: each warp grid-strides over 32-point warp-tiles with a
// double-buffered cp.async gather pipeline (tile i+1's gather in flight
// while tile i computes/stores).
__global__ __launch_bounds__(256, 7) void sd_pipe_kernel(
    const float* __restrict__ points,        // [Q,3]
    const int*   __restrict__ closest_faces, // [Q]
    const float* __restrict__ closest_bcs,   // [Q,3]
    float* __restrict__ out,
    int Q)
{
    // 8 warps x 2 slots x 32 records x 48B (stride 48B -> conflict-free LDS.128)
    __shared__ float4 s_face[8][2][96];      // 24 KB

    int tid  = threadIdx.x;
    int lane = tid & 31;
    int wrp  = tid >> 5;
    int c    = lane & 3;
    int pgrp = lane >> 2;

    int NT = (Q + 31) >> 5;                  // warp-tiles
    int W  = gridDim.x * 8;                  // total warps
    int wt = blockIdx.x * 8 + wrp;

    uint32_t slot0 = (uint32_t)__cvta_generic_to_shared(&s_face[wrp][0][0]);
    uint32_t slot1 = (uint32_t)__cvta_generic_to_shared(&s_face[wrp][1][0]);

    float* rn_out = out + (size_t)Q;
    float* cp_out = out + (size_t)4 * Q;
    float* cf_out = out + (size_t)7 * Q;
    float* bc_out = out + (size_t)8 * Q;

    // prologue: first tile's gather
    if (wt < NT) issue_gather(closest_faces, wt, Q, c, pgrp, slot0);
    cp_commit();

    int cur = 0;
    for (; wt < NT; wt += W) {
        int q = (wt << 5) + lane;
        bool act = (q < Q);
        int qe = act ? q : (Q - 1);

        // stream loads for this tile (overlap any residual gather latency)
        int   f  = closest_faces[qe];
        float c0 = closest_bcs[3*qe + 0];
        float c1 = closest_bcs[3*qe + 1];
        float c2 = closest_bcs[3*qe + 2];
        float p0 = points[3*qe + 0];
        float p1 = points[3*qe + 1];
        float p2 = points[3*qe + 2];

        cp_wait0();
        __syncwarp();

        // issue LDS for this tile's records (slot cur) ...
        const float4* sw = (cur == 0) ? &s_face[wrp][0][0] : &s_face[wrp][1][0];
        float4 v0 = sw[lane*3 + 0];
        float4 v1 = sw[lane*3 + 1];
        float4 v2 = sw[lane*3 + 2];

        // ... and immediately fire next tile's gather into the OTHER slot
        // (disjoint buffers -> no race; flies across compute+stores)
        int wtn = wt + W;
        if (wtn < NT) {
            issue_gather(closest_faces, wtn, Q, c, pgrp, cur ? slot0 : slot1);
        }
        cp_commit();

        float b0 = fminf(fmaxf(c0, 0.0f), 1.0f);
        float b1 = fminf(fmaxf(c1, 0.0f), 1.0f);
        float b2 = fminf(fmaxf(c2, 0.0f), 1.0f);

        // v0=(t00,t01,t02,t10) v1=(t11,t12,t20,t21) v2=(t22,n0,n1,n2)
        float cpx = fmaf(v0.x, b0, fmaf(v0.w, b1, v1.z * b2));
        float cpy = fmaf(v0.y, b0, fmaf(v1.x, b1, v1.w * b2));
        float cpz = fmaf(v0.z, b0, fmaf(v1.y, b1, v2.x * b2));

        float r0 = cpx - p0;
        float r1 = cpy - p1;
        float r2 = cpz - p2;

        float sq   = fmaf(r0, r0, fmaf(r1, r1, r2 * r2));
        float dist = sqrtf(sq);
        float inv  = (dist == 0.0f) ? 1.0f : (1.0f / dist);

        float rn0 = r0 * inv, rn1 = r1 * inv, rn2 = r2 * inv;

        float dot  = fmaf(r0, v2.y, fmaf(r1, v2.z, r2 * v2.w));
        float sign = (dot > 0.0f) ? -1.0f : 1.0f;

        if (act) {
            out[q]    = sign * dist;
            cf_out[q] = (float)f;
            rn_out[3*q+0] = rn0; rn_out[3*q+1] = rn1; rn_out[3*q+2] = rn2;
            cp_out[3*q+0] = cpx; cp_out[3*q+1] = cpy; cp_out[3*q+2] = cpz;
            bc_out[3*q+0] = b0;  bc_out[3*q+1] = b1;  bc_out[3*q+2] = b2;
        }
        cur ^= 1;
    }
}

extern "C" void kernel_launch(void* const* d_in, const int* in_sizes, int n_in,
                              void* d_out, int out_size) {
    const float* triangles     = (const float*)d_in[0];
    const float* face_normals  = (const float*)d_in[1];
    const float* points        = (const float*)d_in[2];
    const int*   closest_faces = (const int*)d_in[3];
    const float* closest_bcs   = (const float*)d_in[4];
    float* out = (float*)d_out;

    int F = in_sizes[0] / 9;
    int Q = in_sizes[3];

    int Fc = F > FMAX ? FMAX : F;
    repack_kernel<<<(Fc * 3 + 255) / 256, 256>>>(triangles, face_normals, Fc);

    sd_pipe_kernel<<<NCTA, 256>>>(points, closest_faces, closest_bcs, out, Q);
}

// round 14
// speedup vs baseline: 1.1792x; 1.1792x over previous
#include <cuda_runtime.h>
#include <cuda_bf16.h>
#include <cstdint>

#define FMAX 20908

// Repacked per-face record: 4 x float4 = 64B, 128B-aligned so each record
// lies in one 128B line.
// chunk0=(t00,t01,t02,t10) chunk1=(t11,t12,t20,t21) chunk2=(t22,n0,n1,n2) chunk3=pad
__device__ __align__(128) float4 g_face_pack[FMAX * 4];

__global__ __launch_bounds__(256) void repack_kernel(
    const float* __restrict__ triangles,    // [F,3,3]
    const float* __restrict__ face_normals, // [F,3]
    int F)
{
    int i = blockIdx.x * blockDim.x + threadIdx.x;
    if (i >= F * 3) return;
    int f = i / 3;
    int c = i - 3 * f;
    const float* t = triangles + (size_t)f * 9;
    float4 v;
    if (c == 0)      v = make_float4(t[0], t[1], t[2], t[3]);
    else if (c == 1) v = make_float4(t[4], t[5], t[6], t[7]);
    else {
        const float* n = face_normals + (size_t)f * 3;
        v = make_float4(t[8], n[0], n[1], n[2]);
    }
    g_face_pack[4*f + c] = v;
}

__device__ __forceinline__ void cp_async16(uint32_t smem_addr, const void* gptr) {
    asm volatile("cp.async.ca.shared.global [%0], [%1], 16;"
                 :: "r"(smem_addr), "l"(gptr) : "memory");
}
__device__ __forceinline__ void cp_commit() {
    asm volatile("cp.async.commit_group;" ::: "memory");
}
__device__ __forceinline__ void cp_wait1() {
    asm volatile("cp.async.wait_group 1;" ::: "memory");
}
__device__ __forceinline__ void cp_wait0() {
    asm volatile("cp.async.wait_group 0;" ::: "memory");
}

// Issue cooperative gather for the 32-point tile starting at base into the
// given smem slot. lane 4p+c copies chunk c (c<3) of point p; face idx via
// L1-hot LDG.
__device__ __forceinline__ void issue_gather(
    const int* __restrict__ closest_faces,
    int base, int Q, int c, int pgrp, uint32_t slot_addr)
{
    #pragma unroll
    for (int r = 0; r < 4; r++) {
        int p_local = 8*r + pgrp;
        int idx = base + p_local;
        if (idx >= Q) idx = Q - 1;
        int fp = closest_faces[idx];
        if (c < 3) {
            cp_async16(slot_addr + (uint32_t)(p_local * 48 + c * 16),
                       &g_face_pack[4*(size_t)fp + c]);
        }
    }
}

// Each warp owns TWO adjacent 32-point tiles. Both gathers are committed as
// separate cp.async groups; wait_group 1 releases tile A while tile B's
// gather (and both tiles' stream loads) are still in flight.
__global__ __launch_bounds__(256, 6) void sd_pipe2_kernel(
    const float* __restrict__ points,        // [Q,3]
    const int*   __restrict__ closest_faces, // [Q]
    const float* __restrict__ closest_bcs,   // [Q,3]
    float* __restrict__ out,
    int Q)
{
    // 8 warps x 2 slots x 32 records x 48B (stride 48B -> conflict-free LDS.128)
    __shared__ float4 s_face[8][2][96];      // 24 KB

    int tid  = threadIdx.x;
    int lane = tid & 31;
    int wrp  = tid >> 5;
    int c    = lane & 3;
    int pgrp = lane >> 2;

    int wbA = blockIdx.x * 512 + wrp * 64;   // warp's first tile base
    if (wbA >= Q) return;                    // uniform per warp
    int wbB = wbA + 32;
    bool hasB = (wbB < Q);

    uint32_t slotA = (uint32_t)__cvta_generic_to_shared(&s_face[wrp][0][0]);
    uint32_t slotB = (uint32_t)__cvta_generic_to_shared(&s_face[wrp][1][0]);

    // fire both gathers (separate groups; complete in order A then B)
    issue_gather(closest_faces, wbA, Q, c, pgrp, slotA);
    cp_commit();
    if (hasB) issue_gather(closest_faces, wbB, Q, c, pgrp, slotB);
    cp_commit();

    // stream loads for both tiles — 14 independent LDGs in flight
    int qA = wbA + lane;
    int qB = wbB + lane;
    int qeA = qA < Q ? qA : (Q - 1);
    int qeB = qB < Q ? qB : (Q - 1);

    int   fA  = closest_faces[qeA];
    float a0 = closest_bcs[3*qeA + 0];
    float a1 = closest_bcs[3*qeA + 1];
    float a2 = closest_bcs[3*qeA + 2];
    float pA0 = points[3*qeA + 0];
    float pA1 = points[3*qeA + 1];
    float pA2 = points[3*qeA + 2];

    int   fB  = closest_faces[qeB];
    float e0 = closest_bcs[3*qeB + 0];
    float e1 = closest_bcs[3*qeB + 1];
    float e2 = closest_bcs[3*qeB + 2];
    float pB0 = points[3*qeB + 0];
    float pB1 = points[3*qeB + 1];
    float pB2 = points[3*qeB + 2];

    float* rn_out = out + (size_t)Q;
    float* cp_out = out + (size_t)4 * Q;
    float* cf_out = out + (size_t)7 * Q;
    float* bc_out = out + (size_t)8 * Q;

    // ---------------- tile A ----------------
    cp_wait1();                              // A's gather done; B still flying
    __syncwarp();
    {
        const float4* sw = &s_face[wrp][0][0];
        float4 v0 = sw[lane*3 + 0];
        float4 v1 = sw[lane*3 + 1];
        float4 v2 = sw[lane*3 + 2];

        float b0 = fminf(fmaxf(a0, 0.0f), 1.0f);
        float b1 = fminf(fmaxf(a1, 0.0f), 1.0f);
        float b2 = fminf(fmaxf(a2, 0.0f), 1.0f);

        // v0=(t00,t01,t02,t10) v1=(t11,t12,t20,t21) v2=(t22,n0,n1,n2)
        float cpx = fmaf(v0.x, b0, fmaf(v0.w, b1, v1.z * b2));
        float cpy = fmaf(v0.y, b0, fmaf(v1.x, b1, v1.w * b2));
        float cpz = fmaf(v0.z, b0, fmaf(v1.y, b1, v2.x * b2));

        float r0 = cpx - pA0, r1 = cpy - pA1, r2 = cpz - pA2;
        float sq   = fmaf(r0, r0, fmaf(r1, r1, r2 * r2));
        float dist = sqrtf(sq);
        float inv  = (dist == 0.0f) ? 1.0f : (1.0f / dist);
        float dot  = fmaf(r0, v2.y, fmaf(r1, v2.z, r2 * v2.w));
        float sign = (dot > 0.0f) ? -1.0f : 1.0f;

        if (qA < Q) {
            out[qA]    = sign * dist;
            cf_out[qA] = (float)fA;
            rn_out[3*qA+0] = r0*inv; rn_out[3*qA+1] = r1*inv; rn_out[3*qA+2] = r2*inv;
            cp_out[3*qA+0] = cpx;    cp_out[3*qA+1] = cpy;    cp_out[3*qA+2] = cpz;
            bc_out[3*qA+0] = b0;     bc_out[3*qA+1] = b1;     bc_out[3*qA+2] = b2;
        }
    }

    // ---------------- tile B ----------------
    if (!hasB) return;
    cp_wait0();
    __syncwarp();
    {
        const float4* sw = &s_face[wrp][1][0];
        float4 v0 = sw[lane*3 + 0];
        float4 v1 = sw[lane*3 + 1];
        float4 v2 = sw[lane*3 + 2];

        float b0 = fminf(fmaxf(e0, 0.0f), 1.0f);
        float b1 = fminf(fmaxf(e1, 0.0f), 1.0f);
        float b2 = fminf(fmaxf(e2, 0.0f), 1.0f);

        float cpx = fmaf(v0.x, b0, fmaf(v0.w, b1, v1.z * b2));
        float cpy = fmaf(v0.y, b0, fmaf(v1.x, b1, v1.w * b2));
        float cpz = fmaf(v0.z, b0, fmaf(v1.y, b1, v2.x * b2));

        float r0 = cpx - pB0, r1 = cpy - pB1, r2 = cpz - pB2;
        float sq   = fmaf(r0, r0, fmaf(r1, r1, r2 * r2));
        float dist = sqrtf(sq);
        float inv  = (dist == 0.0f) ? 1.0f : (1.0f / dist);
        float dot  = fmaf(r0, v2.y, fmaf(r1, v2.z, r2 * v2.w));
        float sign = (dot > 0.0f) ? -1.0f : 1.0f;

        if (qB < Q) {
            out[qB]    = sign * dist;
            cf_out[qB] = (float)fB;
            rn_out[3*qB+0] = r0*inv; rn_out[3*qB+1] = r1*inv; rn_out[3*qB+2] = r2*inv;
            cp_out[3*qB+0] = cpx;    cp_out[3*qB+1] = cpy;    cp_out[3*qB+2] = cpz;
            bc_out[3*qB+0] = b0;     bc_out[3*qB+1] = b1;     bc_out[3*qB+2] = b2;
        }
    }
}

extern "C" void kernel_launch(void* const* d_in, const int* in_sizes, int n_in,
                              void* d_out, int out_size) {
    const float* triangles     = (const float*)d_in[0];
    const float* face_normals  = (const float*)d_in[1];
    const float* points        = (const float*)d_in[2];
    const int*   closest_faces = (const int*)d_in[3];
    const float* closest_bcs   = (const float*)d_in[4];
    float* out = (float*)d_out;

    int F = in_sizes[0] / 9;
    int Q = in_sizes[3];

    int Fc = F > FMAX ? FMAX : F;
    repack_kernel<<<(Fc * 3 + 255) / 256, 256>>>(triangles, face_normals, Fc);

    int blocks = (Q + 511) / 512;
    sd_pipe2_kernel<<<blocks, 256>>>(points, closest_faces, closest_bcs, out, Q);
}